// round 5
// baseline (speedup 1.0000x reference)
#include <cuda_runtime.h>
#include <math.h>

// ---------------------------------------------------------------------------
// Scratch (allocation-free rule: __device__ globals; zero-init at module load)
// ---------------------------------------------------------------------------
#define MAXN        131072
#define EDGE_BLOCKS 2368      // proven R2/R4 config (~70us edge pass)
#define NODE_BLOCKS 148
#define NODE_TPB    256

__device__ float        g_in_sums[MAXN];   // zero at load; node_kernel re-zeroes
__device__ float        g_out_sums[MAXN];
// g_acc: [0]=cov [1]=tour [2]=demand [3]=masked_sq [4]=mask_cnt [5]=focal
__device__ double       g_acc[8];          // zero at load; finalize resets
__device__ float        g_depot_in, g_depot_out;
__device__ unsigned int g_done;            // zero at load; finalize resets

// ---------------------------------------------------------------------------
// Block reduction (warp shuffle + shared)
// ---------------------------------------------------------------------------
__device__ __forceinline__ float block_reduce_sum(float v, float* sh) {
    const int lane = threadIdx.x & 31;
    const int wid  = threadIdx.x >> 5;
    #pragma unroll
    for (int o = 16; o > 0; o >>= 1) v += __shfl_down_sync(0xffffffffu, v, o);
    if (lane == 0) sh[wid] = v;
    __syncthreads();
    v = (threadIdx.x < (blockDim.x >> 5)) ? sh[threadIdx.x] : 0.0f;
    if (wid == 0) {
        #pragma unroll
        for (int o = 16; o > 0; o >>= 1) v += __shfl_down_sync(0xffffffffu, v, o);
    }
    __syncthreads();
    return v;   // valid in thread 0
}

// ---------------------------------------------------------------------------
// Kernel 1: edge pass (UNCHANGED hot loop — proven ~70us)
//   p = sigmoid(l) scattered into in/out segment sums (2 float RED / edge)
//   focal partial -> block reduce -> double atomicAdd (hidden under mainloop)
// Index dtype detected per-block: int64 indices < 2^31 have zero high words;
// an int32 buffer has random indices there (P[32 zeros] ~ 1e-160).
// ---------------------------------------------------------------------------
__device__ __forceinline__ void edge_body(float l, float t, int s, int d,
                                          float& fsum) {
    float z = __expf(-fabsf(l));
    float r = __fdividef(1.0f, 1.0f + z);
    float p = (l >= 0.0f) ? r : (1.0f - r);
    float bce = fmaxf(l, 0.0f) - l * t + __logf(1.0f + z);
    float ompt = p + t - 2.0f * p * t;
    float at   = 0.75f - 0.5f * t;
    fsum = fmaf(at * ompt * ompt, bce, fsum);
    atomicAdd(&g_out_sums[s], p);
    atomicAdd(&g_in_sums[d], p);
}

__global__ void __launch_bounds__(256)
edge_kernel(const float* __restrict__ ep, const float* __restrict__ ye,
            const void* __restrict__ ei, int E) {
    __shared__ float sh[32];
    __shared__ int   sh_is64;

    if (threadIdx.x == 0) {
        const int* w = (const int*)ei;
        int all_hi_zero = 1;
        #pragma unroll
        for (int k = 0; k < 32; k++)
            if (w[2 * k + 1] != 0) { all_hi_zero = 0; break; }
        sh_is64 = all_hi_zero;
    }
    __syncthreads();
    const bool is64 = (sh_is64 != 0);

    float fsum = 0.0f;
    const int tid    = blockIdx.x * blockDim.x + threadIdx.x;
    const int stride = gridDim.x * blockDim.x;

    int base = tid * 4;

    if (!is64) {
        const int* __restrict__ src = (const int*)ei;
        const int* __restrict__ dst = src + E;
        for (; base + 3 < E; base += stride * 4) {
            float4 l4 = *reinterpret_cast<const float4*>(ep + base);
            float4 t4 = *reinterpret_cast<const float4*>(ye + base);
            int4   s4 = *reinterpret_cast<const int4*>(src + base);
            int4   d4 = *reinterpret_cast<const int4*>(dst + base);
            edge_body(l4.x, t4.x, s4.x, d4.x, fsum);
            edge_body(l4.y, t4.y, s4.y, d4.y, fsum);
            edge_body(l4.z, t4.z, s4.z, d4.z, fsum);
            edge_body(l4.w, t4.w, s4.w, d4.w, fsum);
        }
        for (int i = base; i < E && i < base + 4; i++)
            edge_body(ep[i], ye[i], src[i], dst[i], fsum);
    } else {
        const long long* __restrict__ src = (const long long*)ei;
        const long long* __restrict__ dst = src + E;
        for (; base + 3 < E; base += stride * 4) {
            float4    l4  = *reinterpret_cast<const float4*>(ep + base);
            float4    t4  = *reinterpret_cast<const float4*>(ye + base);
            longlong2 s01 = *reinterpret_cast<const longlong2*>(src + base);
            longlong2 s23 = *reinterpret_cast<const longlong2*>(src + base + 2);
            longlong2 d01 = *reinterpret_cast<const longlong2*>(dst + base);
            longlong2 d23 = *reinterpret_cast<const longlong2*>(dst + base + 2);
            edge_body(l4.x, t4.x, (int)s01.x, (int)d01.x, fsum);
            edge_body(l4.y, t4.y, (int)s01.y, (int)d01.y, fsum);
            edge_body(l4.z, t4.z, (int)s23.x, (int)d23.x, fsum);
            edge_body(l4.w, t4.w, (int)s23.y, (int)d23.y, fsum);
        }
        for (int i = base; i < E && i < base + 4; i++)
            edge_body(ep[i], ye[i], (int)src[i], (int)dst[i], fsum);
    }

    float bsum = block_reduce_sum(fsum, sh);
    if (threadIdx.x == 0) atomicAdd(&g_acc[5], (double)bsum);  // hidden by mainloop
}

// ---------------------------------------------------------------------------
// Kernel 2: node pass — grid-stride over nodes, re-zero in/out inline,
//   float block reduce -> double atomicAdd (5 per block, 148 blocks),
//   last block: finalize from 6 scalars only (no partial-array loops).
// ---------------------------------------------------------------------------
__global__ void __launch_bounds__(NODE_TPB)
node_kernel(const float* __restrict__ node_pred,
            const float* __restrict__ x,
            const float* __restrict__ y_nodes,
            const float* __restrict__ capacity,
            float* __restrict__ out,
            int N, int E) {
    __shared__ float shf[32];
    __shared__ bool  is_last;

    const float4* __restrict__ x4 = (const float4*)x;

    float cov = 0.0f, tour = 0.0f, dem = 0.0f, sq = 0.0f, cnt = 0.0f;

    for (int i = blockIdx.x * blockDim.x + threadIdx.x; i < N;
         i += gridDim.x * blockDim.x) {
        float ins  = g_in_sums[i];
        float outs = g_out_sums[i];
        g_in_sums[i]  = 0.0f;          // restore zero invariant for next replay
        g_out_sums[i] = 0.0f;
        float diff = ins - outs;
        tour += diff * diff;
        if (i > 0) {
            float a = ins - 1.0f, b = outs - 1.0f;
            cov += a * a + b * b;
            dem += x4[i].z;            // x[i,2] via one LDG.128
        } else {
            g_depot_in  = ins;
            g_depot_out = outs;
        }
        float y = y_nodes[i];
        float m = (y >= 0.0f) ? 1.0f : 0.0f;
        float e = node_pred[i] - y;
        sq  += m * e * e;
        cnt += m;
    }

    float v;
    v = block_reduce_sum(cov,  shf); if (threadIdx.x == 0) atomicAdd(&g_acc[0], (double)v);
    v = block_reduce_sum(tour, shf); if (threadIdx.x == 0) atomicAdd(&g_acc[1], (double)v);
    v = block_reduce_sum(dem,  shf); if (threadIdx.x == 0) atomicAdd(&g_acc[2], (double)v);
    v = block_reduce_sum(sq,   shf); if (threadIdx.x == 0) atomicAdd(&g_acc[3], (double)v);
    v = block_reduce_sum(cnt,  shf); if (threadIdx.x == 0) atomicAdd(&g_acc[4], (double)v);

    if (threadIdx.x == 0) {
        __threadfence();
        unsigned t = atomicAdd(&g_done, 1u);
        is_last = (t == (unsigned)(gridDim.x - 1));
    }
    __syncthreads();
    if (!is_last || threadIdx.x != 0) return;

    // ---- last block, single thread: 6 scalar reads + combine ----
    double cov_s   = g_acc[0];
    double tour_s  = g_acc[1];
    double dem_s   = g_acc[2];
    double sq_s    = g_acc[3];
    double cnt_s   = g_acc[4];
    double focal_s = g_acc[5];

    double coverage  = cov_s / (2.0 * (double)((N - 1) > 1 ? (N - 1) : 1));
    double tour_t    = tour_s / (double)N;
    double in0  = (double)g_depot_in;
    double out0 = (double)g_depot_out;
    double depot = (in0 - out0) * (in0 - out0);
    double cap_value = (double)capacity[0];     // mean of 1 element
    double expected_tours = ceil(dem_s / cap_value);
    double capacity_tours = (out0 - expected_tours) * (out0 - expected_tours);
    double similarity = focal_s / (double)E;
    double node_loss  = sq_s / fmax(cnt_s, 1.0);
    double total = coverage * 5.0 + tour_t * 3.0 + depot * 2.0 +
                   capacity_tours * 1.5 + similarity * 0.3 + node_loss * 0.1;
    out[0] = (float)total;

    // reset accumulators + counter for next graph replay
    #pragma unroll
    for (int q = 0; q < 6; q++) g_acc[q] = 0.0;
    g_done = 0u;
}

// ---------------------------------------------------------------------------
// kernel_launch — 2 launches per call
// Inputs (metadata order):
//   0: edge_predictions f32 [E]     4: y_edges    f32 [E]
//   1: node_predictions f32 [N]     5: y_nodes    f32 [N]
//   2: x                f32 [N,4]   6: edge_index [2,E] (i32/i64 auto-detected)
//   3: capacity         f32 [1]     7: num_nodes  (ignored; N = in_sizes[1])
// ---------------------------------------------------------------------------
extern "C" void kernel_launch(void* const* d_in, const int* in_sizes, int n_in,
                              void* d_out, int out_size) {
    const float* ep  = (const float*)d_in[0];
    const float* npr = (const float*)d_in[1];
    const float* x   = (const float*)d_in[2];
    const float* cap = (const float*)d_in[3];
    const float* ye  = (const float*)d_in[4];
    const float* yn  = (const float*)d_in[5];
    const void*  ei  = d_in[6];

    const int E = in_sizes[0];
    const int N = in_sizes[1];

    float* out = (float*)d_out;

    // 1. edge pass
    edge_kernel<<<EDGE_BLOCKS, 256>>>(ep, ye, ei, E);
    // 2. node pass + re-zero + fused finalize
    node_kernel<<<NODE_BLOCKS, NODE_TPB>>>(npr, x, yn, cap, out, N, E);
}

// round 6
// speedup vs baseline: 1.1748x; 1.1748x over previous
#include <cuda_runtime.h>
#include <math.h>

// ---------------------------------------------------------------------------
// Scratch (allocation-free rule: __device__ globals; zero-init at module load)
// ---------------------------------------------------------------------------
#define MAXN        131072
#define EDGE_BLOCKS 2368      // proven config (~69-73us edge pass)
#define NODE_TPB    256

__device__ float  g_in_sums[MAXN];
__device__ float  g_out_sums[MAXN];
__device__ float  g_edge_partial[EDGE_BLOCKS];
// g_acc: [0]=cov [1]=tour [2]=demand [3]=masked_sq [4]=mask_cnt
__device__ double g_acc[8];
__device__ float  g_depot_in, g_depot_out;

// ---------------------------------------------------------------------------
// Kernel 1: zero scratch + reset accumulators (runs first every replay).
// Proven cheap (4.2us) and keeps all later kernels store-free / protocol-free.
// ---------------------------------------------------------------------------
__global__ void zero_kernel(int n4) {
    int i = blockIdx.x * blockDim.x + threadIdx.x;
    if (i < n4) {
        reinterpret_cast<float4*>(g_in_sums)[i]  = make_float4(0.f, 0.f, 0.f, 0.f);
        reinterpret_cast<float4*>(g_out_sums)[i] = make_float4(0.f, 0.f, 0.f, 0.f);
    }
    if (blockIdx.x == 0 && threadIdx.x < 8) g_acc[threadIdx.x] = 0.0;
}

// ---------------------------------------------------------------------------
// Block reductions (warp shuffle + shared)
// ---------------------------------------------------------------------------
__device__ __forceinline__ float block_reduce_sum(float v, float* sh) {
    const int lane = threadIdx.x & 31;
    const int wid  = threadIdx.x >> 5;
    #pragma unroll
    for (int o = 16; o > 0; o >>= 1) v += __shfl_down_sync(0xffffffffu, v, o);
    if (lane == 0) sh[wid] = v;
    __syncthreads();
    v = (threadIdx.x < (blockDim.x >> 5)) ? sh[threadIdx.x] : 0.0f;
    if (wid == 0) {
        #pragma unroll
        for (int o = 16; o > 0; o >>= 1) v += __shfl_down_sync(0xffffffffu, v, o);
    }
    __syncthreads();
    return v;   // valid in thread 0
}

__device__ __forceinline__ double block_reduce_sum_d(double v, double* sh) {
    const int lane = threadIdx.x & 31;
    const int wid  = threadIdx.x >> 5;
    #pragma unroll
    for (int o = 16; o > 0; o >>= 1) v += __shfl_down_sync(0xffffffffu, v, o);
    if (lane == 0) sh[wid] = v;
    __syncthreads();
    v = (threadIdx.x < (blockDim.x >> 5)) ? sh[threadIdx.x] : 0.0;
    if (wid == 0) {
        #pragma unroll
        for (int o = 16; o > 0; o >>= 1) v += __shfl_down_sync(0xffffffffu, v, o);
    }
    __syncthreads();
    return v;   // valid in thread 0
}

// ---------------------------------------------------------------------------
// Kernel 2: edge pass (R4 hot loop — best inferred ~69us; tail = plain store)
//   p = sigmoid(l) scattered into in/out segment sums (2 float RED / edge)
//   focal partial -> per-block plain store
// Index dtype detected per-block: int64 indices < 2^31 have zero high words;
// an int32 buffer has random indices there (P[32 zeros] ~ 1e-160).
// ---------------------------------------------------------------------------
__device__ __forceinline__ void edge_body(float l, float t, int s, int d,
                                          float& fsum) {
    float z = __expf(-fabsf(l));
    float r = __fdividef(1.0f, 1.0f + z);
    float p = (l >= 0.0f) ? r : (1.0f - r);
    float bce = fmaxf(l, 0.0f) - l * t + __logf(1.0f + z);
    float ompt = p + t - 2.0f * p * t;
    float at   = 0.75f - 0.5f * t;
    fsum = fmaf(at * ompt * ompt, bce, fsum);
    atomicAdd(&g_out_sums[s], p);
    atomicAdd(&g_in_sums[d], p);
}

__global__ void __launch_bounds__(256)
edge_kernel(const float* __restrict__ ep, const float* __restrict__ ye,
            const void* __restrict__ ei, int E) {
    __shared__ float sh[32];
    __shared__ int   sh_is64;

    if (threadIdx.x == 0) {
        const int* w = (const int*)ei;
        int all_hi_zero = 1;
        #pragma unroll
        for (int k = 0; k < 32; k++)
            if (w[2 * k + 1] != 0) { all_hi_zero = 0; break; }
        sh_is64 = all_hi_zero;
    }
    __syncthreads();
    const bool is64 = (sh_is64 != 0);

    float fsum = 0.0f;
    const int tid    = blockIdx.x * blockDim.x + threadIdx.x;
    const int stride = gridDim.x * blockDim.x;

    int base = tid * 4;

    if (!is64) {
        const int* __restrict__ src = (const int*)ei;
        const int* __restrict__ dst = src + E;
        for (; base + 3 < E; base += stride * 4) {
            float4 l4 = *reinterpret_cast<const float4*>(ep + base);
            float4 t4 = *reinterpret_cast<const float4*>(ye + base);
            int4   s4 = *reinterpret_cast<const int4*>(src + base);
            int4   d4 = *reinterpret_cast<const int4*>(dst + base);
            edge_body(l4.x, t4.x, s4.x, d4.x, fsum);
            edge_body(l4.y, t4.y, s4.y, d4.y, fsum);
            edge_body(l4.z, t4.z, s4.z, d4.z, fsum);
            edge_body(l4.w, t4.w, s4.w, d4.w, fsum);
        }
        for (int i = base; i < E && i < base + 4; i++)
            edge_body(ep[i], ye[i], src[i], dst[i], fsum);
    } else {
        const long long* __restrict__ src = (const long long*)ei;
        const long long* __restrict__ dst = src + E;
        for (; base + 3 < E; base += stride * 4) {
            float4    l4  = *reinterpret_cast<const float4*>(ep + base);
            float4    t4  = *reinterpret_cast<const float4*>(ye + base);
            longlong2 s01 = *reinterpret_cast<const longlong2*>(src + base);
            longlong2 s23 = *reinterpret_cast<const longlong2*>(src + base + 2);
            longlong2 d01 = *reinterpret_cast<const longlong2*>(dst + base);
            longlong2 d23 = *reinterpret_cast<const longlong2*>(dst + base + 2);
            edge_body(l4.x, t4.x, (int)s01.x, (int)d01.x, fsum);
            edge_body(l4.y, t4.y, (int)s01.y, (int)d01.y, fsum);
            edge_body(l4.z, t4.z, (int)s23.x, (int)d23.x, fsum);
            edge_body(l4.w, t4.w, (int)s23.y, (int)d23.y, fsum);
        }
        for (int i = base; i < E && i < base + 4; i++)
            edge_body(ep[i], ye[i], (int)src[i], (int)dst[i], fsum);
    }

    float bsum = block_reduce_sum(fsum, sh);
    if (threadIdx.x == 0) g_edge_partial[blockIdx.x] = bsum;   // plain store
}

// ---------------------------------------------------------------------------
// Kernel 3: node pass — READ-ONLY (R2-proven 7.3us shape).
//   One thread per node, 5 fused reductions -> 5 double atomicAdds per block.
// ---------------------------------------------------------------------------
__global__ void __launch_bounds__(NODE_TPB)
node_kernel(const float* __restrict__ node_pred,
            const float* __restrict__ x,
            const float* __restrict__ y_nodes,
            int N) {
    __shared__ float shf[32];

    const float4* __restrict__ x4 = (const float4*)x;
    const int i = blockIdx.x * blockDim.x + threadIdx.x;

    float cov = 0.0f, tour = 0.0f, dem = 0.0f, sq = 0.0f, cnt = 0.0f;

    if (i < N) {
        float ins  = g_in_sums[i];
        float outs = g_out_sums[i];
        float diff = ins - outs;
        tour = diff * diff;
        if (i > 0) {
            float a = ins - 1.0f, b = outs - 1.0f;
            cov = a * a + b * b;
            dem = x4[i].z;             // x[i,2] via one LDG.128
        } else {
            g_depot_in  = ins;
            g_depot_out = outs;
        }
        float y = y_nodes[i];
        float m = (y >= 0.0f) ? 1.0f : 0.0f;
        float e = node_pred[i] - y;
        sq  = m * e * e;
        cnt = m;
    }

    float v;
    v = block_reduce_sum(cov,  shf); if (threadIdx.x == 0) atomicAdd(&g_acc[0], (double)v);
    v = block_reduce_sum(tour, shf); if (threadIdx.x == 0) atomicAdd(&g_acc[1], (double)v);
    v = block_reduce_sum(dem,  shf); if (threadIdx.x == 0) atomicAdd(&g_acc[2], (double)v);
    v = block_reduce_sum(sq,   shf); if (threadIdx.x == 0) atomicAdd(&g_acc[3], (double)v);
    v = block_reduce_sum(cnt,  shf); if (threadIdx.x == 0) atomicAdd(&g_acc[4], (double)v);
}

// ---------------------------------------------------------------------------
// Kernel 4: finalize — one block, parallel reduce of edge partials + combine.
// ---------------------------------------------------------------------------
__global__ void __launch_bounds__(256)
finalize_kernel(const float* __restrict__ capacity,
                float* __restrict__ out, int N, int E) {
    __shared__ double shd[32];

    double fs = 0.0;
    for (int b = threadIdx.x; b < EDGE_BLOCKS; b += blockDim.x)
        fs += (double)g_edge_partial[b];
    double focal_s = block_reduce_sum_d(fs, shd);

    if (threadIdx.x != 0) return;

    double coverage  = g_acc[0] / (2.0 * (double)((N - 1) > 1 ? (N - 1) : 1));
    double tour_t    = g_acc[1] / (double)N;
    double in0  = (double)g_depot_in;
    double out0 = (double)g_depot_out;
    double depot = (in0 - out0) * (in0 - out0);
    double cap_value = (double)capacity[0];     // mean of 1 element
    double expected_tours = ceil(g_acc[2] / cap_value);
    double capacity_tours = (out0 - expected_tours) * (out0 - expected_tours);
    double similarity = focal_s / (double)E;
    double node_loss  = g_acc[3] / fmax(g_acc[4], 1.0);
    double total = coverage * 5.0 + tour_t * 3.0 + depot * 2.0 +
                   capacity_tours * 1.5 + similarity * 0.3 + node_loss * 0.1;
    out[0] = (float)total;
}

// ---------------------------------------------------------------------------
// kernel_launch — 4 launches per call
// Inputs (metadata order):
//   0: edge_predictions f32 [E]     4: y_edges    f32 [E]
//   1: node_predictions f32 [N]     5: y_nodes    f32 [N]
//   2: x                f32 [N,4]   6: edge_index [2,E] (i32/i64 auto-detected)
//   3: capacity         f32 [1]     7: num_nodes  (ignored; N = in_sizes[1])
// ---------------------------------------------------------------------------
extern "C" void kernel_launch(void* const* d_in, const int* in_sizes, int n_in,
                              void* d_out, int out_size) {
    const float* ep  = (const float*)d_in[0];
    const float* npr = (const float*)d_in[1];
    const float* x   = (const float*)d_in[2];
    const float* cap = (const float*)d_in[3];
    const float* ye  = (const float*)d_in[4];
    const float* yn  = (const float*)d_in[5];
    const void*  ei  = d_in[6];

    const int E = in_sizes[0];
    const int N = in_sizes[1];

    float* out = (float*)d_out;

    // 1. zero scratch + reset accumulators
    {
        int n4 = (N + 3) / 4;
        int blocks = (n4 + 255) / 256;
        zero_kernel<<<blocks, 256>>>(n4);
    }
    // 2. edge pass
    edge_kernel<<<EDGE_BLOCKS, 256>>>(ep, ye, ei, E);
    // 3. node pass (read-only, one thread per node)
    {
        int blocks = (N + NODE_TPB - 1) / NODE_TPB;
        node_kernel<<<blocks, NODE_TPB>>>(npr, x, yn, N);
    }
    // 4. finalize
    finalize_kernel<<<1, 256>>>(cap, out, N, E);
}

// round 7
// speedup vs baseline: 1.2100x; 1.0299x over previous
#include <cuda_runtime.h>
#include <math.h>

// ---------------------------------------------------------------------------
// Scratch (allocation-free rule: __device__ globals; zero-init at module load)
// ---------------------------------------------------------------------------
#define MAXN        131072
#define EDGE_BLOCKS 2368      // proven config (~64us edge pass)
#define NODE_TPB    256

__device__ float        g_in_sums[MAXN];
__device__ float        g_out_sums[MAXN];
// g_acc: [0]=cov [1]=tour [2]=demand [3]=masked_sq [4]=mask_cnt [5]=focal
__device__ double       g_acc[8];
__device__ float        g_depot_in, g_depot_out;
__device__ unsigned int g_done;    // zero at load; last node block resets

// ---------------------------------------------------------------------------
// Kernel 1: zero scratch + reset accumulators (proven 4.2us)
// ---------------------------------------------------------------------------
__global__ void zero_kernel(int n4) {
    int i = blockIdx.x * blockDim.x + threadIdx.x;
    if (i < n4) {
        reinterpret_cast<float4*>(g_in_sums)[i]  = make_float4(0.f, 0.f, 0.f, 0.f);
        reinterpret_cast<float4*>(g_out_sums)[i] = make_float4(0.f, 0.f, 0.f, 0.f);
    }
    if (blockIdx.x == 0 && threadIdx.x < 8) g_acc[threadIdx.x] = 0.0;
}

// ---------------------------------------------------------------------------
// Block reduction (warp shuffle + shared)
// ---------------------------------------------------------------------------
__device__ __forceinline__ float block_reduce_sum(float v, float* sh) {
    const int lane = threadIdx.x & 31;
    const int wid  = threadIdx.x >> 5;
    #pragma unroll
    for (int o = 16; o > 0; o >>= 1) v += __shfl_down_sync(0xffffffffu, v, o);
    if (lane == 0) sh[wid] = v;
    __syncthreads();
    v = (threadIdx.x < (blockDim.x >> 5)) ? sh[threadIdx.x] : 0.0f;
    if (wid == 0) {
        #pragma unroll
        for (int o = 16; o > 0; o >>= 1) v += __shfl_down_sync(0xffffffffu, v, o);
    }
    __syncthreads();
    return v;   // valid in thread 0
}

// ---------------------------------------------------------------------------
// Kernel 2: edge pass (proven hot loop; tail = double atomicAdd, hidden
//   under the ~64us mainloop per R2 evidence)
//   p = sigmoid(l) scattered into in/out segment sums (2 float RED / edge)
// Index dtype detected per-block: int64 indices < 2^31 have zero high words;
// an int32 buffer has random indices there (P[32 zeros] ~ 1e-160).
// ---------------------------------------------------------------------------
__device__ __forceinline__ void edge_body(float l, float t, int s, int d,
                                          float& fsum) {
    float z = __expf(-fabsf(l));
    float r = __fdividef(1.0f, 1.0f + z);
    float p = (l >= 0.0f) ? r : (1.0f - r);
    float bce = fmaxf(l, 0.0f) - l * t + __logf(1.0f + z);
    float ompt = p + t - 2.0f * p * t;
    float at   = 0.75f - 0.5f * t;
    fsum = fmaf(at * ompt * ompt, bce, fsum);
    atomicAdd(&g_out_sums[s], p);
    atomicAdd(&g_in_sums[d], p);
}

__global__ void __launch_bounds__(256)
edge_kernel(const float* __restrict__ ep, const float* __restrict__ ye,
            const void* __restrict__ ei, int E) {
    __shared__ float sh[32];
    __shared__ int   sh_is64;

    if (threadIdx.x == 0) {
        const int* w = (const int*)ei;
        int all_hi_zero = 1;
        #pragma unroll
        for (int k = 0; k < 32; k++)
            if (w[2 * k + 1] != 0) { all_hi_zero = 0; break; }
        sh_is64 = all_hi_zero;
    }
    __syncthreads();
    const bool is64 = (sh_is64 != 0);

    float fsum = 0.0f;
    const int tid    = blockIdx.x * blockDim.x + threadIdx.x;
    const int stride = gridDim.x * blockDim.x;

    int base = tid * 4;

    if (!is64) {
        const int* __restrict__ src = (const int*)ei;
        const int* __restrict__ dst = src + E;
        for (; base + 3 < E; base += stride * 4) {
            float4 l4 = *reinterpret_cast<const float4*>(ep + base);
            float4 t4 = *reinterpret_cast<const float4*>(ye + base);
            int4   s4 = *reinterpret_cast<const int4*>(src + base);
            int4   d4 = *reinterpret_cast<const int4*>(dst + base);
            edge_body(l4.x, t4.x, s4.x, d4.x, fsum);
            edge_body(l4.y, t4.y, s4.y, d4.y, fsum);
            edge_body(l4.z, t4.z, s4.z, d4.z, fsum);
            edge_body(l4.w, t4.w, s4.w, d4.w, fsum);
        }
        for (int i = base; i < E && i < base + 4; i++)
            edge_body(ep[i], ye[i], src[i], dst[i], fsum);
    } else {
        const long long* __restrict__ src = (const long long*)ei;
        const long long* __restrict__ dst = src + E;
        for (; base + 3 < E; base += stride * 4) {
            float4    l4  = *reinterpret_cast<const float4*>(ep + base);
            float4    t4  = *reinterpret_cast<const float4*>(ye + base);
            longlong2 s01 = *reinterpret_cast<const longlong2*>(src + base);
            longlong2 s23 = *reinterpret_cast<const longlong2*>(src + base + 2);
            longlong2 d01 = *reinterpret_cast<const longlong2*>(dst + base);
            longlong2 d23 = *reinterpret_cast<const longlong2*>(dst + base + 2);
            edge_body(l4.x, t4.x, (int)s01.x, (int)d01.x, fsum);
            edge_body(l4.y, t4.y, (int)s01.y, (int)d01.y, fsum);
            edge_body(l4.z, t4.z, (int)s23.x, (int)d23.x, fsum);
            edge_body(l4.w, t4.w, (int)s23.y, (int)d23.y, fsum);
        }
        for (int i = base; i < E && i < base + 4; i++)
            edge_body(ep[i], ye[i], (int)src[i], (int)dst[i], fsum);
    }

    float bsum = block_reduce_sum(fsum, sh);
    if (threadIdx.x == 0) atomicAdd(&g_acc[5], (double)bsum);  // hidden by mainloop
}

// ---------------------------------------------------------------------------
// Kernel 3: node pass — READ-ONLY hot path (proven 7.3us shape) + last-block
//   scalar finalize (6 L2 reads + combine; replaces the 10.2us finalize launch)
// ---------------------------------------------------------------------------
__global__ void __launch_bounds__(NODE_TPB)
node_kernel(const float* __restrict__ node_pred,
            const float* __restrict__ x,
            const float* __restrict__ y_nodes,
            const float* __restrict__ capacity,
            float* __restrict__ out,
            int N, int E) {
    __shared__ float shf[32];
    __shared__ bool  is_last;

    const float4* __restrict__ x4 = (const float4*)x;
    const int i = blockIdx.x * blockDim.x + threadIdx.x;

    float cov = 0.0f, tour = 0.0f, dem = 0.0f, sq = 0.0f, cnt = 0.0f;

    if (i < N) {
        float ins  = g_in_sums[i];
        float outs = g_out_sums[i];
        float diff = ins - outs;
        tour = diff * diff;
        if (i > 0) {
            float a = ins - 1.0f, b = outs - 1.0f;
            cov = a * a + b * b;
            dem = x4[i].z;             // x[i,2] via one LDG.128
        } else {
            g_depot_in  = ins;
            g_depot_out = outs;
        }
        float y = y_nodes[i];
        float m = (y >= 0.0f) ? 1.0f : 0.0f;
        float e = node_pred[i] - y;
        sq  = m * e * e;
        cnt = m;
    }

    float v;
    v = block_reduce_sum(cov,  shf); if (threadIdx.x == 0) atomicAdd(&g_acc[0], (double)v);
    v = block_reduce_sum(tour, shf); if (threadIdx.x == 0) atomicAdd(&g_acc[1], (double)v);
    v = block_reduce_sum(dem,  shf); if (threadIdx.x == 0) atomicAdd(&g_acc[2], (double)v);
    v = block_reduce_sum(sq,   shf); if (threadIdx.x == 0) atomicAdd(&g_acc[3], (double)v);
    v = block_reduce_sum(cnt,  shf); if (threadIdx.x == 0) atomicAdd(&g_acc[4], (double)v);

    if (threadIdx.x == 0) {
        __threadfence();
        unsigned t = atomicAdd(&g_done, 1u);
        is_last = (t == (unsigned)(gridDim.x - 1));
    }
    __syncthreads();
    if (!is_last || threadIdx.x != 0) return;

    // ---- last block, single thread: 6 scalar reads + combine ----
    double coverage  = g_acc[0] / (2.0 * (double)((N - 1) > 1 ? (N - 1) : 1));
    double tour_t    = g_acc[1] / (double)N;
    double in0  = (double)g_depot_in;
    double out0 = (double)g_depot_out;
    double depot = (in0 - out0) * (in0 - out0);
    double cap_value = (double)capacity[0];     // mean of 1 element
    double expected_tours = ceil(g_acc[2] / cap_value);
    double capacity_tours = (out0 - expected_tours) * (out0 - expected_tours);
    double similarity = g_acc[5] / (double)E;
    double node_loss  = g_acc[3] / fmax(g_acc[4], 1.0);
    double total = coverage * 5.0 + tour_t * 3.0 + depot * 2.0 +
                   capacity_tours * 1.5 + similarity * 0.3 + node_loss * 0.1;
    out[0] = (float)total;

    g_done = 0u;    // reset for next graph replay (g_acc reset by zero_kernel)
}

// ---------------------------------------------------------------------------
// kernel_launch — 3 launches per call
// Inputs (metadata order):
//   0: edge_predictions f32 [E]     4: y_edges    f32 [E]
//   1: node_predictions f32 [N]     5: y_nodes    f32 [N]
//   2: x                f32 [N,4]   6: edge_index [2,E] (i32/i64 auto-detected)
//   3: capacity         f32 [1]     7: num_nodes  (ignored; N = in_sizes[1])
// ---------------------------------------------------------------------------
extern "C" void kernel_launch(void* const* d_in, const int* in_sizes, int n_in,
                              void* d_out, int out_size) {
    const float* ep  = (const float*)d_in[0];
    const float* npr = (const float*)d_in[1];
    const float* x   = (const float*)d_in[2];
    const float* cap = (const float*)d_in[3];
    const float* ye  = (const float*)d_in[4];
    const float* yn  = (const float*)d_in[5];
    const void*  ei  = d_in[6];

    const int E = in_sizes[0];
    const int N = in_sizes[1];

    float* out = (float*)d_out;

    // 1. zero scratch + reset accumulators
    {
        int n4 = (N + 3) / 4;
        int blocks = (n4 + 255) / 256;
        zero_kernel<<<blocks, 256>>>(n4);
    }
    // 2. edge pass
    edge_kernel<<<EDGE_BLOCKS, 256>>>(ep, ye, ei, E);
    // 3. node pass + fused scalar finalize
    {
        int blocks = (N + NODE_TPB - 1) / NODE_TPB;
        node_kernel<<<blocks, NODE_TPB>>>(npr, x, yn, cap, out, N, E);
    }
}